// round 7
// baseline (speedup 1.0000x reference)
#include <cuda_runtime.h>

typedef unsigned long long u64;

#define BB 32
#define NN 256
#define NF 16
#define NL 3
#define NODES (BB*NN)
#define WPB 4   // warps (dst nodes) per block

// ping-pong state; precomputed node terms double-buffered by layer parity
__device__ float4 g_x[2][NODES];
__device__ float  g_h[2][NODES*NF];
__device__ u64    g_A2[2][NODES*(NF/2)];    // packed pairs: h_i @ We1[0:NF]
__device__ u64    g_Bjb2[2][NODES*(NF/2)];  // packed pairs: h_j @ We1[NF:2NF] + be1
__device__ float  g_hWh[2][NODES*NF];       // h_j @ Wh1[0:NF] + bh1
__device__ float  g_hv[2][NODES];           // h_j @ W_v

// ---- packed fp32x2 helpers (sm_103a FFMA2 path, PTX-only) ----
__device__ __forceinline__ u64 pk(float lo, float hi) {
    u64 r; asm("mov.b64 %0, {%1,%2};" : "=l"(r) : "f"(lo), "f"(hi)); return r;
}
__device__ __forceinline__ float2 upk(u64 v) {
    float2 r; asm("mov.b64 {%0,%1}, %2;" : "=f"(r.x), "=f"(r.y) : "l"(v)); return r;
}
__device__ __forceinline__ void f2fma_acc(u64& d, u64 a, u64 b) {
    asm("fma.rn.f32x2 %0, %1, %2, %0;" : "+l"(d) : "l"(a), "l"(b));
}
__device__ __forceinline__ u64 f2fma(u64 a, u64 b, u64 c) {
    u64 d; asm("fma.rn.f32x2 %0, %1, %2, %3;" : "=l"(d) : "l"(a), "l"(b), "l"(c)); return d;
}
__device__ __forceinline__ u64 f2add(u64 a, u64 b) {
    u64 d; asm("add.rn.f32x2 %0, %1, %2;" : "=l"(d) : "l"(a), "l"(b)); return d;
}

// init: node features h from charges, plus layer-0 node-side precompute (buffer 0)
__global__ void init_kernel(const float* __restrict__ xs,
                            const float* __restrict__ charges,
                            const float* __restrict__ W_in,
                            const float* __restrict__ b_in,
                            const float* __restrict__ W_v,
                            const float* __restrict__ We1,
                            const float* __restrict__ be1,
                            const float* __restrict__ Wh1,
                            const float* __restrict__ bh1) {
    int gid = blockIdx.x * blockDim.x + threadIdx.x;
    int node = gid >> 4;
    int k = gid & 15;
    if (node >= NODES) return;
    float c = charges[node];
    float h[NF];
    #pragma unroll
    for (int f = 0; f < NF; f++) {
        float v = fmaf(c, W_in[f], b_in[f]);
        h[f] = v > 0.f ? v : 0.f;
    }
    g_h[0][node*NF + k] = h[k];
    float a = 0.f, bb = 0.f, hw = 0.f;
    #pragma unroll
    for (int f = 0; f < NF; f++) {
        a  = fmaf(h[f], We1[f*NF + k],      a);
        bb = fmaf(h[f], We1[(NF+f)*NF + k], bb);
        hw = fmaf(h[f], Wh1[f*NF + k],      hw);
    }
    ((float*)g_A2[0])[node*NF + k]   = a;
    ((float*)g_Bjb2[0])[node*NF + k] = bb + be1[k];
    g_hWh[0][node*NF + k] = hw + bh1[k];
    if (k == 0) {
        float hv = 0.f;
        #pragma unroll
        for (int f = 0; f < NF; f++) hv = fmaf(h[f], W_v[f], hv);
        g_hv[0][node] = hv;
        float4 x;
        x.x = xs[node*3 + 0]; x.y = xs[node*3 + 1]; x.z = xs[node*3 + 2]; x.w = 0.f;
        g_x[0][node] = x;
    }
}

__global__ void __launch_bounds__(WPB*32, 4)
edge_kernel(int l, int cur, int nxt, int last,
            const float* __restrict__ We1,
            const float* __restrict__ be1,
            const float* __restrict__ We2,
            const float* __restrict__ be2,
            const float* __restrict__ Wx,
            const float* __restrict__ Wh1,
            const float* __restrict__ bh1,
            const float* __restrict__ W_v,
            const float* __restrict__ vs,
            float* __restrict__ out) {
    __shared__ u64        sAT[8*NN];      // [q*NN + i]; reused as weight scratch in epilogue
    __shared__ float4     sX[NN];
    __shared__ ulonglong2 sWe2v[NF*4];    // row f at [f*4..f*4+3]
    __shared__ ulonglong2 sBe2[4];        // be2[l] as 8 packed pairs
    __shared__ ulonglong2 sWxv[4];        // Wx[l]  as 8 packed pairs
    __shared__ float      sWh1b[NF*NF];   // Wh1 m_agg half [f][k]
    __shared__ float      sHn[WPB*NF];

    int tid  = threadIdx.x;
    int lane = tid & 31;
    int warp = tid >> 5;
    int b     = blockIdx.x >> 6;          // NN/WPB = 64 blocks per batch
    int jbase = (blockIdx.x & 63) * WPB;
    int nbase = b * NN;

    int pc = l & 1;        // precompute buffer for this layer
    int pn = pc ^ 1;       // precompute buffer for next layer

    // cooperative tile loads
    for (int idx = tid; idx < NN*8; idx += WPB*32) {
        int i = idx >> 3, q = idx & 7;
        sAT[q*NN + i] = g_A2[pc][(nbase + i)*8 + q];
    }
    for (int i = tid; i < NN; i += WPB*32) sX[i] = g_x[cur][nbase + i];
    if (tid < NF*4) sWe2v[tid] = ((const ulonglong2*)We2)[l*(NF*NF/4) + tid];
    if (tid >= 64 && tid < 68) sBe2[tid-64] = ((const ulonglong2*)be2)[l*4 + (tid-64)];
    if (tid >= 68 && tid < 72) sWxv[tid-68] = ((const ulonglong2*)Wx)[l*4 + (tid-68)];
    for (int idx = tid; idx < NF*NF; idx += WPB*32) {
        int f = idx >> 4, k = idx & 15;
        sWh1b[idx] = Wh1[l*(2*NF)*NF + (NF + f)*NF + k];
    }
    __syncthreads();

    int j = jbase + warp;
    int node = nbase + j;

    // per-warp packed constants kept in registers (32 regs total)
    u64 Bjb2[8], wr2[8];
    const u64* wrp = (const u64*)We1 + (l*(2*NF+1)*NF + 2*NF*NF)/2;  // r2 row of We1
    #pragma unroll
    for (int q = 0; q < 8; q++) {
        Bjb2[q] = g_Bjb2[pc][node*8 + q];
        wr2[q]  = wrp[q];
    }
    float4 xj = sX[j];

    u64 magg2[8];
    #pragma unroll
    for (int q = 0; q < 8; q++) magg2[q] = 0ull;
    float ax = 0.f, ay = 0.f, az = 0.f;

    for (int it = 0; it < NN/32; it++) {
        int i = it*32 + lane;
        float4 xi = sX[i];
        float dx = xj.x - xi.x;
        float dy = xj.y - xi.y;
        float dz = xj.z - xi.z;
        float r2 = fmaf(dx, dx, fmaf(dy, dy, dz*dz));
        u64 r22 = pk(r2, r2);

        // t = relu(A_i + B_j + r2*wr)
        float t[NF];
        #pragma unroll
        for (int q = 0; q < 8; q++) {
            u64 ab = f2add(sAT[q*NN + i], Bjb2[q]);
            float2 tv = upk(f2fma(r22, wr2[q], ab));
            t[2*q]   = fmaxf(tv.x, 0.f);
            t[2*q+1] = fmaxf(tv.y, 0.f);
        }

        // m = t @ We2 + be2 (bias from shared, not registers)
        u64 m2[8];
        {
            ulonglong2 b0 = sBe2[0], b1 = sBe2[1], b2 = sBe2[2], b3 = sBe2[3];
            m2[0] = b0.x; m2[1] = b0.y; m2[2] = b1.x; m2[3] = b1.y;
            m2[4] = b2.x; m2[5] = b2.y; m2[6] = b3.x; m2[7] = b3.y;
        }
        #pragma unroll
        for (int f = 0; f < NF; f++) {
            u64 tf2 = pk(t[f], t[f]);
            ulonglong2 wa = sWe2v[f*4 + 0];
            ulonglong2 wb = sWe2v[f*4 + 1];
            ulonglong2 wc = sWe2v[f*4 + 2];
            ulonglong2 wd = sWe2v[f*4 + 3];
            f2fma_acc(m2[0], tf2, wa.x); f2fma_acc(m2[1], tf2, wa.y);
            f2fma_acc(m2[2], tf2, wb.x); f2fma_acc(m2[3], tf2, wb.y);
            f2fma_acc(m2[4], tf2, wc.x); f2fma_acc(m2[5], tf2, wc.y);
            f2fma_acc(m2[6], tf2, wd.x); f2fma_acc(m2[7], tf2, wd.y);
        }

        // relu, w = m·Wx (Wx from shared), magg masked
        float maskf = (i == j) ? 0.f : 1.f;
        u64 mask2 = pk(maskf, maskf);
        u64 wacc = 0ull;
        ulonglong2 x0 = sWxv[0], x1 = sWxv[1], x2 = sWxv[2], x3 = sWxv[3];
        u64 wxp[8] = {x0.x, x0.y, x1.x, x1.y, x2.x, x2.y, x3.x, x3.y};
        #pragma unroll
        for (int q = 0; q < 8; q++) {
            float2 mv = upk(m2[q]);
            u64 mk2 = pk(fmaxf(mv.x, 0.f), fmaxf(mv.y, 0.f));
            f2fma_acc(wacc, mk2, wxp[q]);
            f2fma_acc(magg2[q], mk2, mask2);
        }
        float2 wv = upk(wacc);
        float w = wv.x + wv.y;
        ax = fmaf(dx, w, ax);
        ay = fmaf(dy, w, ay);
        az = fmaf(dz, w, az);
    }

    // warp butterfly reductions
    #pragma unroll
    for (int q = 0; q < 8; q++) {
        #pragma unroll
        for (int off = 16; off; off >>= 1)
            magg2[q] = f2add(magg2[q], __shfl_xor_sync(0xffffffffu, magg2[q], off));
    }
    #pragma unroll
    for (int off = 16; off; off >>= 1) {
        ax += __shfl_xor_sync(0xffffffffu, ax, off);
        ay += __shfl_xor_sync(0xffffffffu, ay, off);
        az += __shfl_xor_sync(0xffffffffu, az, off);
    }

    if (lane == 0) {
        float hv = g_hv[pc][node];
        const float inv = 1.f / (NN - 1);
        float ox = xj.x + ax*inv + vs[node*3 + 0]*hv;
        float oy = xj.y + ay*inv + vs[node*3 + 1]*hv;
        float oz = xj.z + az*inv + vs[node*3 + 2]*hv;
        if (last) {
            out[node*3 + 0] = ox;
            out[node*3 + 1] = oy;
            out[node*3 + 2] = oz;
        } else {
            g_x[nxt][node] = make_float4(ox, oy, oz, 0.f);
        }
    }

    if (!last) {   // uniform branch: syncthreads legal
        // stage next-layer node-precompute weights in shared (reuse sAT region)
        float* sW = (float*)sAT;   // [0:256) We1A, [256:512) We1B, [512:768) Wh1A, [768:784) W_v
        int l1 = l + 1;
        __syncthreads();           // all sAT reads done
        {
            const float* we1n = We1 + l1*(2*NF+1)*NF;
            const float* wh1n = Wh1 + l1*(2*NF)*NF;
            for (int idx = tid; idx < 512; idx += WPB*32) sW[idx]       = we1n[idx];
            for (int idx = tid; idx < 256; idx += WPB*32) sW[512 + idx] = wh1n[idx];
            if (tid < NF) sW[768 + tid] = W_v[l1*NF + tid];
        }

        // h update (uses sWh1b, separate buffer, still valid)
        float maggv[NF];
        #pragma unroll
        for (int q = 0; q < 8; q++) {
            float2 v = upk(magg2[q]);
            maggv[2*q] = v.x; maggv[2*q+1] = v.y;
        }
        if (lane < NF) {
            float g = g_hWh[pc][node*NF + lane];
            #pragma unroll
            for (int f = 0; f < NF; f++) g = fmaf(maggv[f], sWh1b[f*NF + lane], g);
            float hn = g_h[cur][node*NF + lane] + (g > 0.f ? g : 0.f);
            g_h[nxt][node*NF + lane] = hn;
            sHn[warp*NF + lane] = hn;
        }
        __syncthreads();           // weights staged + sHn visible

        // fused next-layer node-side precompute -> buffer pn (no reader this launch)
        if (lane < NF) {
            float a = 0.f, bb = 0.f, hw = 0.f;
            #pragma unroll
            for (int f = 0; f < NF; f++) {
                float hf = sHn[warp*NF + f];
                a  = fmaf(hf, sW[f*NF + lane],        a);
                bb = fmaf(hf, sW[256 + f*NF + lane],  bb);
                hw = fmaf(hf, sW[512 + f*NF + lane],  hw);
            }
            ((float*)g_A2[pn])[node*NF + lane]   = a;
            ((float*)g_Bjb2[pn])[node*NF + lane] = bb + be1[l1*NF + lane];
            g_hWh[pn][node*NF + lane] = hw + bh1[l1*NF + lane];
        } else if (lane == NF) {
            float hv = 0.f;
            #pragma unroll
            for (int f = 0; f < NF; f++) hv = fmaf(sHn[warp*NF + f], sW[768 + f], hv);
            g_hv[pn][node] = hv;
        }
    }
}

extern "C" void kernel_launch(void* const* d_in, const int* in_sizes, int n_in,
                              void* d_out, int out_size) {
    const float* xs      = (const float*)d_in[0];
    const float* vs      = (const float*)d_in[1];
    const float* charges = (const float*)d_in[2];
    const float* W_in    = (const float*)d_in[3];
    const float* b_in    = (const float*)d_in[4];
    const float* W_v     = (const float*)d_in[5];
    const float* We1     = (const float*)d_in[6];
    const float* be1     = (const float*)d_in[7];
    const float* We2     = (const float*)d_in[8];
    const float* be2     = (const float*)d_in[9];
    const float* Wx      = (const float*)d_in[10];
    const float* Wh1     = (const float*)d_in[11];
    const float* bh1     = (const float*)d_in[12];
    float* out = (float*)d_out;

    init_kernel<<<(NODES*NF + 255)/256, 256>>>(xs, charges, W_in, b_in,
                                               W_v, We1, be1, Wh1, bh1);
    int cur = 0;
    for (int l = 0; l < NL; l++) {
        int nxt = cur ^ 1;
        edge_kernel<<<BB*(NN/WPB), WPB*32>>>(l, cur, nxt, (l == NL-1) ? 1 : 0,
                                             We1, be1, We2, be2, Wx, Wh1, bh1, W_v,
                                             vs, out);
        cur = nxt;
    }
}